// round 6
// baseline (speedup 1.0000x reference)
#include <cuda_runtime.h>
#include <cstdint>

// imgs (B,L,M,C,H,W) f32, ts2img_weights (B,L,M) f32
// out (B,L,K,H,W) f32: out[b,l,k] = s * imgs[b,l,topk_idx(k),0]
// s = (1 - w_sel) + w_sel. Non-selected straight-through terms are exactly 0.

#define B_ 32
#define L_ 7
#define M_ 6
#define C_ 3
#define H_ 128
#define W_ 128
#define K_ 3
#define HW_ (H_ * W_)                 // 16384 floats per slice (64 KB)
#define NSLICE_ (B_ * L_ * K_)        // 672
#define THREADS_ 256
#define CHUNK_F_ 4096                 // floats per chunk
#define CHUNK_B_ (CHUNK_F_ * 4)       // 16 KB
#define NCHUNK_ (HW_ / CHUNK_F_)      // 4 chunks per slice
#define SCALE_ITERS_ (CHUNK_F_ / 4 / THREADS_)  // 4 float4 per thread

__device__ __forceinline__ uint32_t smem_u32(const void* p) {
    uint32_t a;
    asm("{ .reg .u64 t; cvta.to.shared.u64 t, %1; cvt.u32.u64 %0, t; }"
        : "=r"(a) : "l"(p));
    return a;
}

__device__ __forceinline__ void mbar_wait_parity(uint32_t mbar, uint32_t parity) {
    uint32_t done;
    asm volatile(
        "{\n\t"
        ".reg .pred p;\n\t"
        "mbarrier.try_wait.parity.acquire.cta.shared::cta.b64 p, [%1], %2;\n\t"
        "selp.b32 %0, 1, 0, p;\n\t"
        "}" : "=r"(done) : "r"(mbar), "r"(parity) : "memory");
    if (!done) {
        asm volatile(
            "{\n\t"
            ".reg .pred P1;\n\t"
            "W_%=:\n\t"
            "mbarrier.try_wait.parity.acquire.cta.shared::cta.b64 P1, [%0], %1, 0x989680;\n\t"
            "@P1 bra.uni D_%=;\n\t"
            "bra.uni W_%=;\n\t"
            "D_%=:\n\t"
            "}" :: "r"(mbar), "r"(parity) : "memory");
    }
}

// One block per (b,l,k) slice. Double-buffered TMA in (G->S) and TMA out
// (S->G, bulk_group): after the prologue each block keeps one read AND one
// write in flight simultaneously -> chip-wide direction mixing.
__global__ __launch_bounds__(THREADS_) void mt2v_kernel(
    const float* __restrict__ imgs,
    const float* __restrict__ wts,
    float* __restrict__ out)
{
    __shared__ alignas(128) float buf[2][CHUNK_F_];     // 2 x 16 KB
    __shared__ alignas(8) unsigned long long mbar[2];

    const int slice = blockIdx.x;
    const int k  = slice % K_;
    const int bl = slice / K_;

    // Redundant per-thread top-k (6 L1-hot loads + a few dozen ALU ops).
    float wv[M_];
#pragma unroll
    for (int m = 0; m < M_; m++) wv[m] = __ldg(&wts[bl * M_ + m]);

    int sel = 0;
    bool used[M_];
#pragma unroll
    for (int m = 0; m < M_; m++) used[m] = false;
#pragma unroll
    for (int kk = 0; kk < K_; kk++) {
        float best = -3.402823466e+38f;
        int bi = 0;
#pragma unroll
        for (int m = 0; m < M_; m++)
            if (!used[m] && wv[m] > best) { best = wv[m]; bi = m; }
        used[bi] = true;
        if (kk == k) sel = bi;
    }
    const float s = (1.0f - wv[sel]) + wv[sel];

    const char* src = (const char*)(imgs + (size_t)(bl * M_ + sel) * (size_t)(C_ * HW_));
    char*       dst = (char*)(out + (size_t)slice * (size_t)HW_);

    const uint32_t mb0 = smem_u32(&mbar[0]);
    const uint32_t mb1 = smem_u32(&mbar[1]);
    const uint32_t ba0 = smem_u32(buf[0]);
    const uint32_t ba1 = smem_u32(buf[1]);

    const bool t0 = (threadIdx.x == 0);
    if (t0) {
        asm volatile("mbarrier.init.shared.b64 [%0], 1;" :: "r"(mb0) : "memory");
        asm volatile("mbarrier.init.shared.b64 [%0], 1;" :: "r"(mb1) : "memory");
    }
    __syncthreads();

    // Prologue: load chunk 0 into buf0.
    if (t0) {
        asm volatile("mbarrier.arrive.expect_tx.shared.b64 _, [%0], %1;"
                     :: "r"(mb0), "r"((uint32_t)CHUNK_B_) : "memory");
        asm volatile("cp.async.bulk.shared::cta.global.mbarrier::complete_tx::bytes "
                     "[%0], [%1], %2, [%3];"
                     :: "r"(ba0), "l"(src), "r"((uint32_t)CHUNK_B_), "r"(mb0)
                     : "memory");
    }

#pragma unroll
    for (int j = 0; j < NCHUNK_; j++) {
        const int      bi = j & 1;
        const uint32_t ph = (uint32_t)((j >> 1) & 1);
        const uint32_t mb = bi ? mb1 : mb0;
        const uint32_t ba = bi ? ba1 : ba0;

        // Wait for load j.
        mbar_wait_parity(mb, ph);

        // Scale in place in smem.
        float4* p = reinterpret_cast<float4*>(buf[bi]);
#pragma unroll
        for (int i = 0; i < SCALE_ITERS_; i++) {
            float4 v = p[threadIdx.x + i * THREADS_];
            v.x *= s; v.y *= s; v.z *= s; v.w *= s;
            p[threadIdx.x + i * THREADS_] = v;
        }
        __syncthreads();   // all scales done + all waiters past phase ph

        if (t0) {
            // Order generic smem writes before the async-proxy read.
            asm volatile("fence.proxy.async.shared::cta;" ::: "memory");
            // Fire-and-forget bulk store S->G for chunk j.
            asm volatile("cp.async.bulk.global.shared::cta.bulk_group [%0], [%1], %2;"
                         :: "l"(dst + (size_t)j * CHUNK_B_), "r"(ba),
                            "r"((uint32_t)CHUNK_B_) : "memory");
            asm volatile("cp.async.bulk.commit_group;" ::: "memory");

            if (j + 1 < NCHUNK_) {
                // Reuse of buf[bi^1] requires store j-1 done; allow store j in flight.
                asm volatile("cp.async.bulk.wait_group 1;" ::: "memory");
                const uint32_t nmb = (bi ^ 1) ? mb1 : mb0;
                const uint32_t nba = (bi ^ 1) ? ba1 : ba0;
                asm volatile("mbarrier.arrive.expect_tx.shared.b64 _, [%0], %1;"
                             :: "r"(nmb), "r"((uint32_t)CHUNK_B_) : "memory");
                asm volatile("cp.async.bulk.shared::cta.global.mbarrier::complete_tx::bytes "
                             "[%0], [%1], %2, [%3];"
                             :: "r"(nba), "l"(src + (size_t)(j + 1) * CHUNK_B_),
                                "r"((uint32_t)CHUNK_B_), "r"(nmb)
                             : "memory");
            }
        }
    }

    // Drain outstanding stores before smem goes away.
    if (t0) {
        asm volatile("cp.async.bulk.wait_group 0;" ::: "memory");
    }
    __syncthreads();
}

extern "C" void kernel_launch(void* const* d_in, const int* in_sizes, int n_in,
                              void* d_out, int out_size)
{
    const float* imgs = (const float*)d_in[0];
    const float* wts  = (const float*)d_in[1];
    float* out        = (float*)d_out;

    mt2v_kernel<<<NSLICE_, THREADS_>>>(imgs, wts, out);
}

// round 9
// speedup vs baseline: 1.0022x; 1.0022x over previous
#include <cuda_runtime.h>
#include <cstdint>

// imgs (B,L,M,C,H,W) f32, ts2img_weights (B,L,M) f32
// out (B,L,K,H,W) f32: out[b,l,k] = s * imgs[b,l,topk_idx(k),0]
// s = (1 - w_sel) + w_sel. Non-selected straight-through terms are exactly 0.

#define B_ 32
#define L_ 7
#define M_ 6
#define C_ 3
#define H_ 128
#define W_ 128
#define K_ 3
#define HW_ (H_ * W_)                       // 16384 floats per slice
#define NSLICE_ (B_ * L_ * K_)              // 672
#define CHUNK_ 8192                         // floats per block
#define CHUNKS_PER_SLICE_ (HW_ / CHUNK_)    // 2
#define THREADS_ 256
#define V8_PER_CHUNK_ (CHUNK_ / 8)          // 1024 v8.b32 packets per chunk
#define VEC_ITERS_ (V8_PER_CHUNK_ / THREADS_) // 4 x 256-bit per thread

struct Desc { int off; float s; };          // src float-offset into imgs, scale
__device__ Desc g_desc[NSLICE_];

// ---- Stage 1: per-(b,l,k) top-k selection -> descriptor -------------------
__global__ void mt2v_desc_kernel(const float* __restrict__ wts)
{
    int idx = blockIdx.x * blockDim.x + threadIdx.x;   // 0 .. NSLICE_-1
    if (idx >= NSLICE_) return;
    int k  = idx % K_;
    int bl = idx / K_;

    float wv[M_];
#pragma unroll
    for (int m = 0; m < M_; m++) wv[m] = __ldg(&wts[bl * M_ + m]);

    // Stable top-k (strict > => lowest index wins ties, matching lax.top_k).
    int sel = 0;
    bool used[M_];
#pragma unroll
    for (int m = 0; m < M_; m++) used[m] = false;
#pragma unroll
    for (int kk = 0; kk < K_; kk++) {
        float best = -3.402823466e+38f;
        int bi = 0;
#pragma unroll
        for (int m = 0; m < M_; m++)
            if (!used[m] && wv[m] > best) { best = wv[m]; bi = m; }
        used[bi] = true;
        if (kk == k) sel = bi;
    }

    Desc d;
    d.off = (bl * M_ + sel) * (C_ * HW_);   // channel 0 of imgs[b,l,sel]
    d.s   = (1.0f - wv[sel]) + wv[sel];
    g_desc[idx] = d;
}

// ---- Stage 2: scaled slice copy, 256-bit ops + L2 evict_last both ways ----
// sm_103a requires .v8.b32/.v4.b64 with L2 cache-hint modifiers. The 88MB
// working set fits the 126MB L2; evict_last pins it so graph replays run
// L2-hit instead of round-tripping DRAM in both directions.
__global__ __launch_bounds__(THREADS_) void mt2v_gather_kernel(
    const float* __restrict__ imgs,
    float* __restrict__ out)
{
    const int blk   = blockIdx.x;
    const int chunk = blk % CHUNKS_PER_SLICE_;
    const int slice = blk / CHUNKS_PER_SLICE_;

    const Desc d = g_desc[slice];           // single 8B load, L2-hot
    const float s = d.s;

    // Byte addressing in 32B packets.
    const char* src = (const char*)(imgs + (size_t)d.off)
                    + (size_t)chunk * (CHUNK_ * 4) + (size_t)threadIdx.x * 32;
    char* dst = (char*)out + (size_t)slice * (HW_ * 4)
              + (size_t)chunk * (CHUNK_ * 4) + (size_t)threadIdx.x * 32;

#pragma unroll
    for (int i = 0; i < VEC_ITERS_; i++) {
        uint32_t r0, r1, r2, r3, r4, r5, r6, r7;
        asm("ld.global.nc.L2::evict_last.v8.b32 {%0,%1,%2,%3,%4,%5,%6,%7}, [%8];"
            : "=r"(r0), "=r"(r1), "=r"(r2), "=r"(r3),
              "=r"(r4), "=r"(r5), "=r"(r6), "=r"(r7)
            : "l"(src + (size_t)i * (THREADS_ * 32)));

        r0 = __float_as_uint(__uint_as_float(r0) * s);
        r1 = __float_as_uint(__uint_as_float(r1) * s);
        r2 = __float_as_uint(__uint_as_float(r2) * s);
        r3 = __float_as_uint(__uint_as_float(r3) * s);
        r4 = __float_as_uint(__uint_as_float(r4) * s);
        r5 = __float_as_uint(__uint_as_float(r5) * s);
        r6 = __float_as_uint(__uint_as_float(r6) * s);
        r7 = __float_as_uint(__uint_as_float(r7) * s);

        asm volatile("st.global.L2::evict_last.v8.b32 [%0], {%1,%2,%3,%4,%5,%6,%7,%8};"
                     :: "l"(dst + (size_t)i * (THREADS_ * 32)),
                        "r"(r0), "r"(r1), "r"(r2), "r"(r3),
                        "r"(r4), "r"(r5), "r"(r6), "r"(r7)
                     : "memory");
    }
}

extern "C" void kernel_launch(void* const* d_in, const int* in_sizes, int n_in,
                              void* d_out, int out_size)
{
    const float* imgs = (const float*)d_in[0];
    const float* wts  = (const float*)d_in[1];
    float* out        = (float*)d_out;

    mt2v_desc_kernel<<<(NSLICE_ + 223) / 224, 224>>>(wts);
    mt2v_gather_kernel<<<NSLICE_ * CHUNKS_PER_SLICE_, THREADS_>>>(imgs, out);
}